// round 1
// baseline (speedup 1.0000x reference)
#include <cuda_runtime.h>
#include <cuda_bf16.h>
#include <cstdint>

// Problem constants
#define BB 4
#define SS 8192
#define DD 1024
#define MM (BB * SS)      // 32768
#define KK DD             // 1024
#define NN3 (3 * DD)      // 3072

// GEMM tiling
#define BM 128
#define BN 64
#define BK 16

// Scan chunking
#define SCAN_C 32
#define SCAN_L (SS / SCAN_C)   // 256
#define NCH (BB * DD)          // 4096 channels

// Scratch (static device allocations — no cudaMalloc allowed)
__device__ float g_logf[(size_t)MM * DD];   // 134 MB
__device__ float g_logv[(size_t)MM * DD];   // 134 MB
__device__ float g_pF[SCAN_C * NCH];
__device__ float g_pH[SCAN_C * NCH];
__device__ float g_carry[SCAN_C * NCH];

__device__ __forceinline__ float sp(float x) {
    // softplus(x) = log(1 + e^x), numerically safe form
    return fmaxf(x, 0.0f) + __logf(1.0f + __expf(-fabsf(x)));
}

__device__ __forceinline__ float logaddexp_f(float a, float b) {
    float m = fmaxf(a, b);
    float n = fminf(a, b);
    return m + __logf(1.0f + __expf(n - m));
}

// ---------------------------------------------------------------------------
// Phase 1: GEMM with fused gate epilogue.
// Each block computes a [BM x BN] tile of d-columns for ALL THREE gates
// (hidden/f/i), reusing the A tile 3x. Epilogue computes log_f and log_values
// and writes them to scratch (2 floats/elem instead of 3 raw gemm outputs).
// ---------------------------------------------------------------------------
__global__ __launch_bounds__(256, 1) void gemm_gates_kernel(
    const float* __restrict__ X, const float* __restrict__ W)
{
    __shared__ float As[BK][BM];
    __shared__ float Bs[3][BK][BN];

    const int tid = threadIdx.x;
    const int m0 = blockIdx.y * BM;
    const int n0 = blockIdx.x * BN;

    const int ty = tid >> 4;   // 0..15 -> 8 rows each
    const int tx = tid & 15;   // 0..15 -> 4 cols each

    float acc[3][8][4];
#pragma unroll
    for (int g = 0; g < 3; ++g)
#pragma unroll
        for (int i = 0; i < 8; ++i)
#pragma unroll
            for (int j = 0; j < 4; ++j) acc[g][i][j] = 0.0f;

    for (int k0 = 0; k0 < KK; k0 += BK) {
        // Load A tile: 128x16 floats = 512 float4, 2 per thread, stored transposed.
#pragma unroll
        for (int it = 0; it < 2; ++it) {
            int id = tid * 2 + it;          // 0..511
            int r  = id >> 2;               // 0..127
            int cg = id & 3;                // 0..3 (group of 4 k-cols)
            float4 v = *(const float4*)(X + (size_t)(m0 + r) * KK + k0 + cg * 4);
            As[cg * 4 + 0][r] = v.x;
            As[cg * 4 + 1][r] = v.y;
            As[cg * 4 + 2][r] = v.z;
            As[cg * 4 + 3][r] = v.w;
        }
        // Load B tiles (3 gates): per gate 16x64 floats = 256 float4, 1 per thread.
#pragma unroll
        for (int g = 0; g < 3; ++g) {
            int r  = tid >> 4;              // 0..15
            int cg = tid & 15;              // 0..15
            float4 v = *(const float4*)(W + (size_t)(k0 + r) * NN3 + g * DD + n0 + cg * 4);
            *(float4*)&Bs[g][r][cg * 4] = v;
        }
        __syncthreads();

#pragma unroll
        for (int k = 0; k < BK; ++k) {
            float a[8];
            float bfr[3][4];
            *(float4*)&a[0] = *(const float4*)&As[k][ty * 8];
            *(float4*)&a[4] = *(const float4*)&As[k][ty * 8 + 4];
#pragma unroll
            for (int g = 0; g < 3; ++g)
                *(float4*)&bfr[g][0] = *(const float4*)&Bs[g][k][tx * 4];
#pragma unroll
            for (int g = 0; g < 3; ++g)
#pragma unroll
                for (int i = 0; i < 8; ++i)
#pragma unroll
                    for (int j = 0; j < 4; ++j)
                        acc[g][i][j] = fmaf(a[i], bfr[g][j], acc[g][i][j]);
        }
        __syncthreads();
    }

    // Fused epilogue: gate math -> log_f, log_values
#pragma unroll
    for (int i = 0; i < 8; ++i) {
        int m = m0 + ty * 8 + i;
#pragma unroll
        for (int j = 0; j < 4; ++j) {
            int d = n0 + tx * 4 + j;
            float h  = acc[0][i][j];
            float fg = acc[1][i][j];
            float ig = acc[2][i][j];

            float diff = sp(-fg) - sp(-ig);
            float lf = -sp(diff);
            float li = -sp(-diff);
            float lg = (h >= 0.0f) ? __logf(h + 0.5f) : -sp(-h);

            size_t idx = (size_t)m * DD + d;
            g_logf[idx] = lf;
            g_logv[idx] = li + lg;
        }
    }
}

// ---------------------------------------------------------------------------
// Phase 2a: per-chunk local scan -> (sum log_f, local log_h)
// grid = (SCAN_C, BB), block = DD threads (thread = one d channel; coalesced)
// ---------------------------------------------------------------------------
__global__ __launch_bounds__(1024) void scan_partial_kernel()
{
    int d = threadIdx.x;
    int c = blockIdx.x;
    int b = blockIdx.y;
    size_t base = ((size_t)b * SS + (size_t)c * SCAN_L) * DD + d;

    float sumF = 0.0f;
    float lH = -1e30f;
    for (int s = 0; s < SCAN_L; ++s) {
        float lf = g_logf[base + (size_t)s * DD];
        float lv = g_logv[base + (size_t)s * DD];
        sumF += lf;
        lH = logaddexp_f(lf + lH, lv);
    }
    int ch = b * DD + d;
    g_pF[c * NCH + ch] = sumF;
    g_pH[c * NCH + ch] = lH;
}

// ---------------------------------------------------------------------------
// Phase 2b: serial combine across the 32 chunks -> carry-in per chunk
// ---------------------------------------------------------------------------
__global__ __launch_bounds__(1024) void scan_combine_kernel()
{
    int d = threadIdx.x;
    int b = blockIdx.x;
    int ch = b * DD + d;
    float st = -1e30f;
#pragma unroll
    for (int c = 0; c < SCAN_C; ++c) {
        g_carry[c * NCH + ch] = st;
        st = logaddexp_f(g_pF[c * NCH + ch] + st, g_pH[c * NCH + ch]);
    }
}

// ---------------------------------------------------------------------------
// Phase 2c: replay local scan with carry-in, write exp(log_h) to output
// ---------------------------------------------------------------------------
__global__ __launch_bounds__(1024) void scan_final_kernel(float* __restrict__ out)
{
    int d = threadIdx.x;
    int c = blockIdx.x;
    int b = blockIdx.y;
    int ch = b * DD + d;
    float lH = g_carry[c * NCH + ch];
    size_t base = ((size_t)b * SS + (size_t)c * SCAN_L) * DD + d;

    for (int s = 0; s < SCAN_L; ++s) {
        float lf = g_logf[base + (size_t)s * DD];
        float lv = g_logv[base + (size_t)s * DD];
        lH = logaddexp_f(lf + lH, lv);
        out[base + (size_t)s * DD] = __expf(lH);
    }
}

extern "C" void kernel_launch(void* const* d_in, const int* in_sizes, int n_in,
                              void* d_out, int out_size)
{
    const float* x = (const float*)d_in[0];   // [B, S, D]
    const float* W = (const float*)d_in[1];   // [D, 3D]
    float* out = (float*)d_out;

    dim3 gemm_grid(DD / BN, MM / BM);         // (16, 256)
    gemm_gates_kernel<<<gemm_grid, 256>>>(x, W);

    scan_partial_kernel<<<dim3(SCAN_C, BB), DD>>>();
    scan_combine_kernel<<<BB, DD>>>();
    scan_final_kernel<<<dim3(SCAN_C, BB), DD>>>(out);
}

// round 3
// speedup vs baseline: 2.3935x; 2.3935x over previous
#include <cuda_runtime.h>
#include <cuda_bf16.h>
#include <cstdint>

// ---------------------------------------------------------------------------
// Problem constants
// ---------------------------------------------------------------------------
#define BB 4
#define SS 8192
#define DD 1024
#define MM (BB * SS)      // 32768
#define N3 (3 * DD)       // 3072

// Scan chunking
#define SCAN_C 32
#define SCAN_L (SS / SCAN_C)   // 256
#define NCH (BB * DD)          // 4096

// GEMM tiling
#define TMT 128            // CTA M tile
#define TNT 64             // CTA N (d) tile per gate
#define KC 32              // bf16 K per chunk
#define NCHUNK 96          // 3 passes x 32
#define ROWB 80            // padded row bytes (64 data + 16 pad) -> conflict-free ldmatrix
#define A_BYTES (TMT * ROWB)          // 10240
#define BG_BYTES (TNT * ROWB)         // 5120
#define STAGEB (A_BYTES + 3 * BG_BYTES)  // 25600
#define NST 3
#define DYN_BYTES (NST * STAGEB)      // 76800

// ---------------------------------------------------------------------------
// Scratch (static device allocations)
// ---------------------------------------------------------------------------
__device__ __nv_bfloat16 g_xhi[(size_t)MM * DD];
__device__ __nv_bfloat16 g_xlo[(size_t)MM * DD];
__device__ __nv_bfloat16 g_whi[(size_t)N3 * DD];  // transposed: [n][k]
__device__ __nv_bfloat16 g_wlo[(size_t)N3 * DD];
__device__ float g_fv[(size_t)MM * DD * 2];       // interleaved (f', val) pairs
__device__ float g_pF[SCAN_C * NCH];
__device__ float g_pH[SCAN_C * NCH];
__device__ float g_carry[SCAN_C * NCH];

// ---------------------------------------------------------------------------
// Portable PTX helpers (valid on plain sm_103 target)
// ---------------------------------------------------------------------------
__device__ __forceinline__ uint32_t smem_u32(const void* p) {
    uint32_t a;
    asm("{ .reg .u64 t; cvta.to.shared.u64 t, %1; cvt.u32.u64 %0, t; }" : "=r"(a) : "l"(p));
    return a;
}
__device__ __forceinline__ void cpa16(uint32_t s, const void* g) {
    asm volatile("cp.async.cg.shared.global [%0], [%1], 16;" :: "r"(s), "l"(g));
}
__device__ __forceinline__ void ldmatrix_x4(uint32_t* r, uint32_t addr) {
    asm volatile("ldmatrix.sync.aligned.m8n8.x4.shared.b16 {%0,%1,%2,%3}, [%4];"
                 : "=r"(r[0]), "=r"(r[1]), "=r"(r[2]), "=r"(r[3]) : "r"(addr));
}
__device__ __forceinline__ void mma_bf16(float* c, const uint32_t* a, uint32_t b0, uint32_t b1) {
    asm volatile(
        "mma.sync.aligned.m16n8k16.row.col.f32.bf16.bf16.f32 "
        "{%0,%1,%2,%3}, {%4,%5,%6,%7}, {%8,%9}, {%0,%1,%2,%3};"
        : "+f"(c[0]), "+f"(c[1]), "+f"(c[2]), "+f"(c[3])
        : "r"(a[0]), "r"(a[1]), "r"(a[2]), "r"(a[3]), "r"(b0), "r"(b1));
}

__device__ __forceinline__ void split_bf16(float v, __nv_bfloat16& hi, __nv_bfloat16& lo) {
    hi = __float2bfloat16_rn(v);
    lo = __float2bfloat16_rn(v - __bfloat162float(hi));
}

// ---------------------------------------------------------------------------
// Convert X -> (xhi, xlo) bf16
// ---------------------------------------------------------------------------
__global__ __launch_bounds__(256) void convert_x_kernel(const float* __restrict__ X) {
    size_t i = (size_t)blockIdx.x * blockDim.x + threadIdx.x;   // float4 index
    float4 v = ((const float4*)X)[i];
    __nv_bfloat16 h0, h1, h2, h3, l0, l1, l2, l3;
    split_bf16(v.x, h0, l0); split_bf16(v.y, h1, l1);
    split_bf16(v.z, h2, l2); split_bf16(v.w, h3, l3);
    __nv_bfloat162* ph = (__nv_bfloat162*)g_xhi;
    __nv_bfloat162* pl = (__nv_bfloat162*)g_xlo;
    ph[2 * i]     = __nv_bfloat162(h0, h1);
    ph[2 * i + 1] = __nv_bfloat162(h2, h3);
    pl[2 * i]     = __nv_bfloat162(l0, l1);
    pl[2 * i + 1] = __nv_bfloat162(l2, l3);
}

// ---------------------------------------------------------------------------
// Convert + transpose W [K=1024, N=3072] -> Wt_hi/lo [N=3072, K=1024]
// ---------------------------------------------------------------------------
__global__ __launch_bounds__(256) void convert_w_kernel(const float* __restrict__ W) {
    __shared__ float tile[32][33];
    int bx = blockIdx.x;   // n tile (96)
    int by = blockIdx.y;   // k tile (32)
    int tx = threadIdx.x;  // 32
    int ty = threadIdx.y;  // 8
#pragma unroll
    for (int i = 0; i < 4; ++i) {
        int k = by * 32 + ty + i * 8;
        tile[ty + i * 8][tx] = W[(size_t)k * N3 + bx * 32 + tx];
    }
    __syncthreads();
#pragma unroll
    for (int i = 0; i < 4; ++i) {
        int n = bx * 32 + ty + i * 8;
        int k = by * 32 + tx;
        float v = tile[tx][ty + i * 8];
        __nv_bfloat16 h, l;
        split_bf16(v, h, l);
        g_whi[(size_t)n * DD + k] = h;
        g_wlo[(size_t)n * DD + k] = l;
    }
}

// ---------------------------------------------------------------------------
// Issue cp.async loads for one K-chunk into one pipeline stage.
// chunk c in [0, NCHUNK): pass = c/32 selects hi/lo operands, kk = (c%32)*32.
// ---------------------------------------------------------------------------
__device__ __forceinline__ void load_chunk(int c, uint32_t sb, int tid, int m0, int n0) {
    const int pass = c >> 5;
    const int kk = (c & 31) * KC;
    const __nv_bfloat16* Asrc = (pass < 2) ? g_xhi : g_xlo;
    const __nv_bfloat16* Bsrc = (pass == 1) ? g_wlo : g_whi;

    // A: 128 rows x 64B (512 x 16B, 2 per thread)
#pragma unroll
    for (int it = 0; it < 2; ++it) {
        int id = tid + it * 256;
        int r = id >> 2, ch = id & 3;
        cpa16(sb + r * ROWB + ch * 16,
              Asrc + (size_t)(m0 + r) * DD + kk + ch * 8);
    }
    // B: 3 gates x 64 rows x 64B (256 x 16B per gate, 1 per thread)
    {
        int r = tid >> 2, ch = tid & 3;
#pragma unroll
        for (int g = 0; g < 3; ++g) {
            cpa16(sb + A_BYTES + g * BG_BYTES + r * ROWB + ch * 16,
                  Bsrc + (size_t)(g * DD + n0 + r) * DD + kk + ch * 8);
        }
    }
    asm volatile("cp.async.commit_group;" ::: "memory");
}

// ---------------------------------------------------------------------------
// bf16 mma.sync GEMM (3-term split) + fused gate epilogue (linear domain).
// CTA: 256 threads (8 warps, 4x2), tile M=128 x N=64, 3 gates in registers.
// ---------------------------------------------------------------------------
__global__ __launch_bounds__(256, 2) void gemm_gates_kernel() {
    extern __shared__ char sm_raw[];
    const uint32_t sbase = smem_u32(sm_raw);

    const int tid = threadIdx.x;
    const int wid = tid >> 5;
    const int lane = tid & 31;
    const int m0 = blockIdx.y * TMT;
    const int n0 = blockIdx.x * TNT;
    const int mw = (wid >> 1) * 32;   // warp m offset in tile
    const int nw = (wid & 1) * 32;    // warp n offset in tile

    // Per-lane ldmatrix address terms (constant across chunks except ks/mt/j)
    const int mat = lane >> 3;
    const uint32_t a_term = (uint32_t)((mw + (mat & 1) * 8 + (lane & 7)) * ROWB + (mat >> 1) * 16);
    const uint32_t b_term = (uint32_t)((nw + (mat >> 1) * 8 + (lane & 7)) * ROWB + (mat & 1) * 16);

    float acc[3][2][4][4];
#pragma unroll
    for (int g = 0; g < 3; ++g)
#pragma unroll
        for (int mt = 0; mt < 2; ++mt)
#pragma unroll
            for (int nt = 0; nt < 4; ++nt)
#pragma unroll
                for (int e = 0; e < 4; ++e) acc[g][mt][nt][e] = 0.0f;

    // Prologue: prefetch chunks 0,1
    load_chunk(0, sbase + 0 * STAGEB, tid, m0, n0);
    load_chunk(1, sbase + 1 * STAGEB, tid, m0, n0);

    int stage = 0;
    for (int c = 0; c < NCHUNK; ++c) {
        asm volatile("cp.async.wait_group 1;" ::: "memory");
        __syncthreads();

        // Prefetch c+2 into the stage freed by chunk c-1 (empty commit keeps
        // group accounting consistent on the tail).
        if (c + 2 < NCHUNK) {
            int ns = stage + 2; if (ns >= NST) ns -= NST;
            load_chunk(c + 2, sbase + ns * STAGEB, tid, m0, n0);
        } else {
            asm volatile("cp.async.commit_group;" ::: "memory");
        }

        const uint32_t sb = sbase + stage * STAGEB;
#pragma unroll
        for (int ks = 0; ks < 2; ++ks) {
            uint32_t a[2][4];
#pragma unroll
            for (int mt = 0; mt < 2; ++mt)
                ldmatrix_x4(a[mt], sb + a_term + mt * 16 * ROWB + ks * 32);
#pragma unroll
            for (int g = 0; g < 3; ++g) {
                uint32_t b[2][4];
                const uint32_t bg = sb + A_BYTES + g * BG_BYTES + b_term + ks * 32;
#pragma unroll
                for (int j = 0; j < 2; ++j)
                    ldmatrix_x4(b[j], bg + j * 16 * ROWB);
#pragma unroll
                for (int mt = 0; mt < 2; ++mt) {
#pragma unroll
                    for (int nt = 0; nt < 4; ++nt)
                        mma_bf16(acc[g][mt][nt], a[mt], b[nt >> 1][(nt & 1) * 2],
                                 b[nt >> 1][(nt & 1) * 2 + 1]);
                }
            }
        }
        stage = stage + 1; if (stage >= NST) stage = 0;
    }

    // ------------------------------------------------------------------
    // Epilogue: gate math in linear domain.
    //   u = 1+e^{-f}, v = 1+e^{-i}, r = 1/(u+v)
    //   f' = v*r, i' = u*r, g = (h>=0) ? h+0.5 : sigmoid(h), val = i'*g
    // Store interleaved (f', val) as float4 per 2 adjacent d.
    // ------------------------------------------------------------------
    const int rbase = lane >> 2;           // 0..7
    const int cbase = 2 * (lane & 3);      // 0,2,4,6
#pragma unroll
    for (int mt = 0; mt < 2; ++mt) {
#pragma unroll
        for (int nt = 0; nt < 4; ++nt) {
#pragma unroll
            for (int half = 0; half < 2; ++half) {
                const int m = m0 + mw + mt * 16 + rbase + half * 8;
                const int d = n0 + nw + nt * 8 + cbase;
                float4 st;
#pragma unroll
                for (int e = 0; e < 2; ++e) {
                    const int ei = half * 2 + e;
                    float h  = acc[0][mt][nt][ei];
                    float fg = acc[1][mt][nt][ei];
                    float ig = acc[2][mt][nt][ei];
                    float u = 1.0f + __expf(-fg);
                    float v = 1.0f + __expf(-ig);
                    float r = __frcp_rn(u + v);
                    float fp = v * r;
                    float ip = u * r;
                    float eh = __expf(fminf(h, 0.0f));
                    float gneg = eh * __frcp_rn(1.0f + eh);
                    float gv = (h >= 0.0f) ? (h + 0.5f) : gneg;
                    if (e == 0) { st.x = fp; st.y = ip * gv; }
                    else        { st.z = fp; st.w = ip * gv; }
                }
                *(float4*)(g_fv + 2 * ((size_t)m * DD + d)) = st;
            }
        }
    }
}

// ---------------------------------------------------------------------------
// Linear-domain scan: h = f*h + val  (pure FMA, memory bound)
// ---------------------------------------------------------------------------
__global__ __launch_bounds__(1024) void scan_partial_kernel() {
    int d = threadIdx.x;
    int c = blockIdx.x;
    int b = blockIdx.y;
    const float2* fv = (const float2*)g_fv;
    size_t base = ((size_t)b * SS + (size_t)c * SCAN_L) * DD + d;
    float F = 1.0f;
    float H = 0.0f;
    for (int s = 0; s < SCAN_L; ++s) {
        float2 p = fv[base + (size_t)s * DD];
        F *= p.x;
        H = fmaf(p.x, H, p.y);
    }
    int ch = b * DD + d;
    g_pF[c * NCH + ch] = F;
    g_pH[c * NCH + ch] = H;
}

__global__ __launch_bounds__(1024) void scan_combine_kernel() {
    int d = threadIdx.x;
    int b = blockIdx.x;
    int ch = b * DD + d;
    float st = 0.0f;
#pragma unroll
    for (int c = 0; c < SCAN_C; ++c) {
        g_carry[c * NCH + ch] = st;
        st = fmaf(g_pF[c * NCH + ch], st, g_pH[c * NCH + ch]);
    }
}

__global__ __launch_bounds__(1024) void scan_final_kernel(float* __restrict__ out) {
    int d = threadIdx.x;
    int c = blockIdx.x;
    int b = blockIdx.y;
    int ch = b * DD + d;
    float h = g_carry[c * NCH + ch];
    const float2* fv = (const float2*)g_fv;
    size_t base = ((size_t)b * SS + (size_t)c * SCAN_L) * DD + d;
    for (int s = 0; s < SCAN_L; ++s) {
        float2 p = fv[base + (size_t)s * DD];
        h = fmaf(p.x, h, p.y);
        out[base + (size_t)s * DD] = h;
    }
}

// ---------------------------------------------------------------------------
extern "C" void kernel_launch(void* const* d_in, const int* in_sizes, int n_in,
                              void* d_out, int out_size)
{
    const float* x = (const float*)d_in[0];   // [B, S, D]
    const float* W = (const float*)d_in[1];   // [D, 3D]
    float* out = (float*)d_out;

    cudaFuncSetAttribute(gemm_gates_kernel,
                         cudaFuncAttributeMaxDynamicSharedMemorySize, DYN_BYTES);

    convert_x_kernel<<<(MM * DD / 4) / 256, 256>>>(x);
    convert_w_kernel<<<dim3(N3 / 32, DD / 32), dim3(32, 8)>>>(W);
    gemm_gates_kernel<<<dim3(DD / TNT, MM / TMT), 256, DYN_BYTES>>>();
    scan_partial_kernel<<<dim3(SCAN_C, BB), DD>>>();
    scan_combine_kernel<<<BB, DD>>>();
    scan_final_kernel<<<dim3(SCAN_C, BB), DD>>>(out);
}

// round 4
// speedup vs baseline: 5.7464x; 2.4008x over previous
#include <cuda_runtime.h>
#include <cuda_bf16.h>
#include <cuda_fp16.h>
#include <cstdint>

// ---------------------------------------------------------------------------
// Problem constants
// ---------------------------------------------------------------------------
#define BB 4
#define SS 8192
#define DD 1024
#define MM (BB * SS)      // 32768
#define N3 (3 * DD)       // 3072

// Scan chunking
#define SCAN_C 32
#define SCAN_L (SS / SCAN_C)   // 256
#define NCH (BB * DD)          // 4096

// GEMM tiling
#define TMT 128            // CTA M tile
#define TNT 64             // CTA N (d) tile per gate
#define KC 32              // fp16 K per chunk
#define NCHUNK 32          // single pass over K=1024
#define ROWB 80            // padded row bytes (64 data + 16 pad) -> conflict-free ldmatrix
#define A_BYTES (TMT * ROWB)          // 10240
#define BG_BYTES (TNT * ROWB)         // 5120
#define STAGEB (A_BYTES + 3 * BG_BYTES)  // 25600
#define NST 3
#define DYN_BYTES (NST * STAGEB)      // 76800

// ---------------------------------------------------------------------------
// Scratch (static device allocations)
// ---------------------------------------------------------------------------
__device__ __half g_xh[(size_t)MM * DD];
__device__ __half g_wh[(size_t)N3 * DD];          // transposed: [n][k]
__device__ float g_fv[(size_t)MM * DD * 2];       // interleaved (f', val) pairs
__device__ float g_pF[SCAN_C * NCH];
__device__ float g_pH[SCAN_C * NCH];
__device__ float g_carry[SCAN_C * NCH];

// ---------------------------------------------------------------------------
// Portable PTX helpers (valid on plain sm_103 target)
// ---------------------------------------------------------------------------
__device__ __forceinline__ uint32_t smem_u32(const void* p) {
    uint32_t a;
    asm("{ .reg .u64 t; cvta.to.shared.u64 t, %1; cvt.u32.u64 %0, t; }" : "=r"(a) : "l"(p));
    return a;
}
__device__ __forceinline__ void cpa16(uint32_t s, const void* g) {
    asm volatile("cp.async.cg.shared.global [%0], [%1], 16;" :: "r"(s), "l"(g));
}
__device__ __forceinline__ void ldmatrix_x4(uint32_t* r, uint32_t addr) {
    asm volatile("ldmatrix.sync.aligned.m8n8.x4.shared.b16 {%0,%1,%2,%3}, [%4];"
                 : "=r"(r[0]), "=r"(r[1]), "=r"(r[2]), "=r"(r[3]) : "r"(addr));
}
__device__ __forceinline__ void mma_fp16(float* c, const uint32_t* a, uint32_t b0, uint32_t b1) {
    asm volatile(
        "mma.sync.aligned.m16n8k16.row.col.f32.f16.f16.f32 "
        "{%0,%1,%2,%3}, {%4,%5,%6,%7}, {%8,%9}, {%0,%1,%2,%3};"
        : "+f"(c[0]), "+f"(c[1]), "+f"(c[2]), "+f"(c[3])
        : "r"(a[0]), "r"(a[1]), "r"(a[2]), "r"(a[3]), "r"(b0), "r"(b1));
}

// ---------------------------------------------------------------------------
// Convert X -> fp16
// ---------------------------------------------------------------------------
__global__ __launch_bounds__(256) void convert_x_kernel(const float* __restrict__ X) {
    size_t i = (size_t)blockIdx.x * blockDim.x + threadIdx.x;   // float4 index
    float4 v = ((const float4*)X)[i];
    __half2* ph = (__half2*)g_xh;
    ph[2 * i]     = __floats2half2_rn(v.x, v.y);
    ph[2 * i + 1] = __floats2half2_rn(v.z, v.w);
}

// ---------------------------------------------------------------------------
// Convert + transpose W [K=1024, N=3072] -> Wt [N=3072, K=1024] fp16
// ---------------------------------------------------------------------------
__global__ __launch_bounds__(256) void convert_w_kernel(const float* __restrict__ W) {
    __shared__ float tile[32][33];
    int bx = blockIdx.x;   // n tile (96)
    int by = blockIdx.y;   // k tile (32)
    int tx = threadIdx.x;  // 32
    int ty = threadIdx.y;  // 8
#pragma unroll
    for (int i = 0; i < 4; ++i) {
        int k = by * 32 + ty + i * 8;
        tile[ty + i * 8][tx] = W[(size_t)k * N3 + bx * 32 + tx];
    }
    __syncthreads();
#pragma unroll
    for (int i = 0; i < 4; ++i) {
        int n = bx * 32 + ty + i * 8;
        int k = by * 32 + tx;
        g_wh[(size_t)n * DD + k] = __float2half_rn(tile[tx][ty + i * 8]);
    }
}

// ---------------------------------------------------------------------------
// Issue cp.async loads for one K-chunk into one pipeline stage.
// ---------------------------------------------------------------------------
__device__ __forceinline__ void load_chunk(int c, uint32_t sb, int tid, int m0, int n0) {
    const int kk = c * KC;

    // A: 128 rows x 64B (512 x 16B, 2 per thread)
#pragma unroll
    for (int it = 0; it < 2; ++it) {
        int id = tid + it * 256;
        int r = id >> 2, ch = id & 3;
        cpa16(sb + r * ROWB + ch * 16,
              g_xh + (size_t)(m0 + r) * DD + kk + ch * 8);
    }
    // B: 3 gates x 64 rows x 64B (256 x 16B per gate, 1 per thread)
    {
        int r = tid >> 2, ch = tid & 3;
#pragma unroll
        for (int g = 0; g < 3; ++g) {
            cpa16(sb + A_BYTES + g * BG_BYTES + r * ROWB + ch * 16,
                  g_wh + (size_t)(g * DD + n0 + r) * DD + kk + ch * 8);
        }
    }
    asm volatile("cp.async.commit_group;" ::: "memory");
}

// ---------------------------------------------------------------------------
// fp16 mma.sync GEMM + fused gate epilogue (linear domain).
// CTA: 256 threads (8 warps, 4x2), tile M=128 x N=64, 3 gates in registers.
// ---------------------------------------------------------------------------
__global__ __launch_bounds__(256, 2) void gemm_gates_kernel() {
    extern __shared__ char sm_raw[];
    const uint32_t sbase = smem_u32(sm_raw);

    const int tid = threadIdx.x;
    const int wid = tid >> 5;
    const int lane = tid & 31;
    const int m0 = blockIdx.y * TMT;
    const int n0 = blockIdx.x * TNT;
    const int mw = (wid >> 1) * 32;   // warp m offset in tile
    const int nw = (wid & 1) * 32;    // warp n offset in tile

    // Per-lane ldmatrix address terms
    const int mat = lane >> 3;
    const uint32_t a_term = (uint32_t)((mw + (mat & 1) * 8 + (lane & 7)) * ROWB + (mat >> 1) * 16);
    const uint32_t b_term = (uint32_t)((nw + (mat >> 1) * 8 + (lane & 7)) * ROWB + (mat & 1) * 16);

    float acc[3][2][4][4];
#pragma unroll
    for (int g = 0; g < 3; ++g)
#pragma unroll
        for (int mt = 0; mt < 2; ++mt)
#pragma unroll
            for (int nt = 0; nt < 4; ++nt)
#pragma unroll
                for (int e = 0; e < 4; ++e) acc[g][mt][nt][e] = 0.0f;

    // Prologue: prefetch chunks 0,1
    load_chunk(0, sbase + 0 * STAGEB, tid, m0, n0);
    load_chunk(1, sbase + 1 * STAGEB, tid, m0, n0);

    int stage = 0;
    for (int c = 0; c < NCHUNK; ++c) {
        asm volatile("cp.async.wait_group 1;" ::: "memory");
        __syncthreads();

        if (c + 2 < NCHUNK) {
            int ns = stage + 2; if (ns >= NST) ns -= NST;
            load_chunk(c + 2, sbase + ns * STAGEB, tid, m0, n0);
        } else {
            asm volatile("cp.async.commit_group;" ::: "memory");
        }

        const uint32_t sb = sbase + stage * STAGEB;
#pragma unroll
        for (int ks = 0; ks < 2; ++ks) {
            uint32_t a[2][4];
#pragma unroll
            for (int mt = 0; mt < 2; ++mt)
                ldmatrix_x4(a[mt], sb + a_term + mt * 16 * ROWB + ks * 32);
#pragma unroll
            for (int g = 0; g < 3; ++g) {
                uint32_t b[2][4];
                const uint32_t bg = sb + A_BYTES + g * BG_BYTES + b_term + ks * 32;
#pragma unroll
                for (int j = 0; j < 2; ++j)
                    ldmatrix_x4(b[j], bg + j * 16 * ROWB);
#pragma unroll
                for (int mt = 0; mt < 2; ++mt) {
#pragma unroll
                    for (int nt = 0; nt < 4; ++nt)
                        mma_fp16(acc[g][mt][nt], a[mt], b[nt >> 1][(nt & 1) * 2],
                                 b[nt >> 1][(nt & 1) * 2 + 1]);
                }
            }
        }
        stage = stage + 1; if (stage >= NST) stage = 0;
    }

    // ------------------------------------------------------------------
    // Epilogue: gate math in linear domain.
    //   u = 1+e^{-f}, v = 1+e^{-i}, r = 1/(u+v)
    //   f' = v*r, i' = u*r, g = (h>=0) ? h+0.5 : sigmoid(h), val = i'*g
    // ------------------------------------------------------------------
    const int rbase = lane >> 2;           // 0..7
    const int cbase = 2 * (lane & 3);      // 0,2,4,6
#pragma unroll
    for (int mt = 0; mt < 2; ++mt) {
#pragma unroll
        for (int nt = 0; nt < 4; ++nt) {
#pragma unroll
            for (int half = 0; half < 2; ++half) {
                const int m = m0 + mw + mt * 16 + rbase + half * 8;
                const int d = n0 + nw + nt * 8 + cbase;
                float4 st;
#pragma unroll
                for (int e = 0; e < 2; ++e) {
                    const int ei = half * 2 + e;
                    float h  = acc[0][mt][nt][ei];
                    float fg = acc[1][mt][nt][ei];
                    float ig = acc[2][mt][nt][ei];
                    float u = 1.0f + __expf(-fg);
                    float v = 1.0f + __expf(-ig);
                    float r = __frcp_rn(u + v);
                    float fp = v * r;
                    float ip = u * r;
                    float eh = __expf(fminf(h, 0.0f));
                    float gneg = eh * __frcp_rn(1.0f + eh);
                    float gv = (h >= 0.0f) ? (h + 0.5f) : gneg;
                    if (e == 0) { st.x = fp; st.y = ip * gv; }
                    else        { st.z = fp; st.w = ip * gv; }
                }
                *(float4*)(g_fv + 2 * ((size_t)m * DD + d)) = st;
            }
        }
    }
}

// ---------------------------------------------------------------------------
// Linear-domain scan: h = f*h + val  (pure FMA, memory bound)
// ---------------------------------------------------------------------------
__global__ __launch_bounds__(1024) void scan_partial_kernel() {
    int d = threadIdx.x;
    int c = blockIdx.x;
    int b = blockIdx.y;
    const float2* fv = (const float2*)g_fv;
    size_t base = ((size_t)b * SS + (size_t)c * SCAN_L) * DD + d;
    float F = 1.0f;
    float H = 0.0f;
    for (int s = 0; s < SCAN_L; ++s) {
        float2 p = fv[base + (size_t)s * DD];
        F *= p.x;
        H = fmaf(p.x, H, p.y);
    }
    int ch = b * DD + d;
    g_pF[c * NCH + ch] = F;
    g_pH[c * NCH + ch] = H;
}

__global__ __launch_bounds__(1024) void scan_combine_kernel() {
    int d = threadIdx.x;
    int b = blockIdx.x;
    int ch = b * DD + d;
    float st = 0.0f;
#pragma unroll
    for (int c = 0; c < SCAN_C; ++c) {
        g_carry[c * NCH + ch] = st;
        st = fmaf(g_pF[c * NCH + ch], st, g_pH[c * NCH + ch]);
    }
}

__global__ __launch_bounds__(1024) void scan_final_kernel(float* __restrict__ out) {
    int d = threadIdx.x;
    int c = blockIdx.x;
    int b = blockIdx.y;
    int ch = b * DD + d;
    float h = g_carry[c * NCH + ch];
    const float2* fv = (const float2*)g_fv;
    size_t base = ((size_t)b * SS + (size_t)c * SCAN_L) * DD + d;
    for (int s = 0; s < SCAN_L; ++s) {
        float2 p = fv[base + (size_t)s * DD];
        h = fmaf(p.x, h, p.y);
        out[base + (size_t)s * DD] = h;
    }
}

// ---------------------------------------------------------------------------
extern "C" void kernel_launch(void* const* d_in, const int* in_sizes, int n_in,
                              void* d_out, int out_size)
{
    const float* x = (const float*)d_in[0];   // [B, S, D]
    const float* W = (const float*)d_in[1];   // [D, 3D]
    float* out = (float*)d_out;

    cudaFuncSetAttribute(gemm_gates_kernel,
                         cudaFuncAttributeMaxDynamicSharedMemorySize, DYN_BYTES);

    convert_x_kernel<<<(MM * DD / 4) / 256, 256>>>(x);
    convert_w_kernel<<<dim3(N3 / 32, DD / 32), dim3(32, 8)>>>(W);
    gemm_gates_kernel<<<dim3(DD / TNT, MM / TMT), 256, DYN_BYTES>>>();
    scan_partial_kernel<<<dim3(SCAN_C, BB), DD>>>();
    scan_combine_kernel<<<BB, DD>>>();
    scan_final_kernel<<<dim3(SCAN_C, BB), DD>>>(out);
}